// round 5
// baseline (speedup 1.0000x reference)
#include <cuda_runtime.h>
#include <cuda_bf16.h>

#define LMAX 13
#define LPAD 14
#define NP 7          // float2 pairs per padded row (LPAD/2)
#define N_TYPES 20
#define NRES_MAX 2048
#define DV 64
#define TPB 192       // = DV * 3

__constant__ int c_res_len[N_TYPES] = {3,4,5,5,6,6,6,7,7,7,7,7,8,8,8,9,10,10,11,13};
__device__ int g_starts[NRES_MAX];

// ---------------------------------------------------------------------------
// Kernel 1: exclusive scan of residue lengths -> g_starts. One block.
// ---------------------------------------------------------------------------
__global__ void scan_starts_kernel(const int* __restrict__ seq, int n_res) {
    __shared__ int s[1024];
    int tid = threadIdx.x;
    int i0 = 2 * tid, i1 = 2 * tid + 1;
    int l0 = (i0 < n_res) ? c_res_len[seq[i0]] : 0;
    int l1 = (i1 < n_res) ? c_res_len[seq[i1]] : 0;
    int pair = l0 + l1;
    s[tid] = pair;
    __syncthreads();
    #pragma unroll
    for (int off = 1; off < 1024; off <<= 1) {
        int v = (tid >= off) ? s[tid - off] : 0;
        __syncthreads();
        s[tid] += v;
        __syncthreads();
    }
    int excl = s[tid] - pair;
    if (i0 < n_res) g_starts[i0] = excl;
    if (i1 < n_res) g_starts[i1] = excl + l0;
}

// scalar element from a float2 array with compile-time index
#define ELEM(arr, l) (((l) & 1) ? arr[(l) >> 1].y : arr[(l) >> 1].x)

// ---------------------------------------------------------------------------
// Templated hot path: exact trip counts for residue length L.
// ---------------------------------------------------------------------------
template<int L>
__device__ __forceinline__ void posmix_body(
    const float2* __restrict__ sW2v,   // sW2 + v*NP  (weight row base for v)
    const float2* __restrict__ sd2d,   // sd2 + d*NP  (diff column base for d)
    const float*  __restrict__ gWa,    // W_amn row for (t, v)
    float* __restrict__ qamn,          // out_amn + i*192 + tid   (batch 0)
    float* __restrict__ patm,          // out_atm + start*192 + tid (batch 0)
    int B, int bstride_amn, int bstride_atm)
{
    constexpr int NPL = (L + 1) / 2;   // float2 pairs covering L (tail zero-padded)

    #pragma unroll 1
    for (int bb0 = 0; bb0 < B; bb0 += 4) {
        // pull 4 batches of this thread's diff column into registers
        float2 dv0[NPL], dv1[NPL], dv2[NPL], dv3[NPL];
        #pragma unroll
        for (int p = 0; p < NPL; p++) {
            dv0[p] = sd2d[(bb0 + 0) * 3 * NP + p];
            dv1[p] = sd2d[(bb0 + 1) * 3 * NP + p];
            dv2[p] = sd2d[(bb0 + 2) * 3 * NP + p];
            dv3[p] = sd2d[(bb0 + 3) * 3 * NP + p];
        }

        // ---- x_v_amn : exact-L dot ----
        {
            float a0 = 0.f, a1 = 0.f, a2 = 0.f, a3 = 0.f;
            #pragma unroll
            for (int l = 0; l < L; l++) {
                float w = gWa[l];           // L1-cached, broadcast across 3 d-threads
                a0 += w * ELEM(dv0, l);
                a1 += w * ELEM(dv1, l);
                a2 += w * ELEM(dv2, l);
                a3 += w * ELEM(dv3, l);
            }
            float* q = qamn + bb0 * bstride_amn;
            q[0] = a0;
            q += bstride_amn; q[0] = a1;
            q += bstride_amn; q[0] = a2;
            q += bstride_amn; q[0] = a3;
        }

        // ---- x_v_atm : L output atoms, exact-L dots ----
        float* p0 = patm + bb0 * bstride_atm;
        float* p1 = p0 + bstride_atm;
        float* p2 = p1 + bstride_atm;
        float* p3 = p2 + bstride_atm;
        #pragma unroll
        for (int m = 0; m < L; m++) {
            const float2* wr = sW2v + m * (DV * NP);
            float a0 = 0.f, a1 = 0.f, a2 = 0.f, a3 = 0.f;
            #pragma unroll
            for (int p = 0; p < NPL; p++) {
                float2 w = wr[p];           // odd-L tail: dv pair .y is 0
                a0 += w.x * dv0[p].x + w.y * dv0[p].y;
                a1 += w.x * dv1[p].x + w.y * dv1[p].y;
                a2 += w.x * dv2[p].x + w.y * dv2[p].y;
                a3 += w.x * dv3[p].x + w.y * dv3[p].y;
            }
            p0[0] = a0; p1[0] = a1; p2[0] = a2; p3[0] = a3;
            p0 += DV * 3; p1 += DV * 3; p2 += DV * 3; p3 += DV * 3;
        }
    }
}

// ---------------------------------------------------------------------------
// Kernel 2: fused gather + dual-einsum + scatter. One block per residue.
// ---------------------------------------------------------------------------
__global__ __launch_bounds__(TPB, 4) void posmix_kernel(
    const float* __restrict__ pos_atm,   // (B, atoms, 3)
    const float* __restrict__ pos_amn,   // (B, n_res, 3)
    const float* __restrict__ W_amn,     // (20, 64, 13)
    const float* __restrict__ W_atm,     // (20, 13, 64, 13)
    const int*   __restrict__ seq,       // (n_res,)
    float* __restrict__ out_atm,         // (B, atoms, 64, 3)
    float* __restrict__ out_amn,         // (B, n_res, 64, 3)
    int B, int n_res, int atoms)
{
    extern __shared__ float smem[];
    float* sW    = smem;                        // LMAX*DV*LPAD floats
    float* sdiff = smem + LMAX * DV * LPAD;     // B*3*LPAD floats

    const int i   = blockIdx.x;
    const int tid = threadIdx.x;
    const int t   = seq[i];
    const int L   = c_res_len[t];
    const int start = g_starts[i];

    // --- stage W_atm[t][0:L][*][*], padded rows of 14 (slot 13 zeroed) ---
    const float* gW = W_atm + (size_t)t * (LMAX * DV * LMAX);
    const int nW = L * DV * LMAX;
    for (int idx = tid; idx < nW; idx += TPB) {
        int row = idx / LMAX;
        int l   = idx - row * LMAX;
        sW[row * LPAD + l] = gW[idx];
    }
    for (int r = tid; r < L * DV; r += TPB) sW[r * LPAD + LMAX] = 0.0f;

    // --- stage diffs, layout [b][d][LPAD], zero-padded in l ---
    const int nd = B * 3 * LPAD;
    for (int idx = tid; idx < nd; idx += TPB) {
        int b = idx / (3 * LPAD);
        int r = idx - b * (3 * LPAD);
        int d = r / LPAD;
        int l = r - d * LPAD;
        float val = 0.0f;
        if (l < L) {
            val = pos_atm[((size_t)b * atoms + start + l) * 3 + d]
                - pos_amn[((size_t)b * n_res + i) * 3 + d];
        }
        sdiff[idx] = val;
    }
    __syncthreads();

    const int v = tid / 3;
    const int d = tid - v * 3;
    const float2* sW2v = (const float2*)sW + v * NP;
    const float2* sd2d = (const float2*)sdiff + d * NP;
    const float*  gWa  = W_amn + ((size_t)t * DV + v) * LMAX;

    const int bstride_atm = atoms * (DV * 3);
    const int bstride_amn = n_res * (DV * 3);

    float* qamn = out_amn + i * (DV * 3) + tid;
    float* patm = out_atm + start * (DV * 3) + tid;

    switch (L) {
        case 3:  posmix_body<3> (sW2v, sd2d, gWa, qamn, patm, B, bstride_amn, bstride_atm); break;
        case 4:  posmix_body<4> (sW2v, sd2d, gWa, qamn, patm, B, bstride_amn, bstride_atm); break;
        case 5:  posmix_body<5> (sW2v, sd2d, gWa, qamn, patm, B, bstride_amn, bstride_atm); break;
        case 6:  posmix_body<6> (sW2v, sd2d, gWa, qamn, patm, B, bstride_amn, bstride_atm); break;
        case 7:  posmix_body<7> (sW2v, sd2d, gWa, qamn, patm, B, bstride_amn, bstride_atm); break;
        case 8:  posmix_body<8> (sW2v, sd2d, gWa, qamn, patm, B, bstride_amn, bstride_atm); break;
        case 9:  posmix_body<9> (sW2v, sd2d, gWa, qamn, patm, B, bstride_amn, bstride_atm); break;
        case 10: posmix_body<10>(sW2v, sd2d, gWa, qamn, patm, B, bstride_amn, bstride_atm); break;
        case 11: posmix_body<11>(sW2v, sd2d, gWa, qamn, patm, B, bstride_amn, bstride_atm); break;
        default: posmix_body<13>(sW2v, sd2d, gWa, qamn, patm, B, bstride_amn, bstride_atm); break;
    }
}

// ---------------------------------------------------------------------------
// Launch: d_out = concat(x_v_atm.ravel(), x_v_amn.ravel())
// ---------------------------------------------------------------------------
extern "C" void kernel_launch(void* const* d_in, const int* in_sizes, int n_in,
                              void* d_out, int out_size) {
    const float* pos_atm = (const float*)d_in[0];
    const float* pos_amn = (const float*)d_in[1];
    const float* W_amn   = (const float*)d_in[2];
    const float* W_atm   = (const float*)d_in[3];
    const int*   seq     = (const int*)d_in[4];

    const int n_res = in_sizes[4];                  // 2048
    const int B     = in_sizes[1] / (n_res * 3);    // 16
    const int atoms = in_sizes[0] / (B * 3);        // 15036

    float* out_atm = (float*)d_out;
    float* out_amn = out_atm + (size_t)B * atoms * DV * 3;

    const int smem_bytes = (LMAX * DV * LPAD + 16 * 3 * LPAD) * (int)sizeof(float);
    cudaFuncSetAttribute(posmix_kernel,
                         cudaFuncAttributeMaxDynamicSharedMemorySize, smem_bytes);

    scan_starts_kernel<<<1, 1024>>>(seq, n_res);
    posmix_kernel<<<n_res, TPB, smem_bytes>>>(pos_atm, pos_amn, W_amn, W_atm, seq,
                                              out_atm, out_amn, B, n_res, atoms);
}

// round 8
// speedup vs baseline: 2.6044x; 2.6044x over previous
#include <cuda_runtime.h>
#include <cuda_bf16.h>

#define LMAX 13
#define LPAD 14
#define NP 7          // float2 pairs per padded smem row (LPAD/2)
#define N_TYPES 20
#define NRES_MAX 2048
#define DV 64
#define TPB 192       // = DV * 3

__constant__ int c_res_len[N_TYPES] = {3,4,5,5,6,6,6,7,7,7,7,7,8,8,8,9,10,10,11,13};
__device__ int g_starts[NRES_MAX];

// ---------------------------------------------------------------------------
// Kernel 1: exclusive scan of residue lengths -> g_starts. One block.
// ---------------------------------------------------------------------------
__global__ void scan_starts_kernel(const int* __restrict__ seq, int n_res) {
    __shared__ int s[1024];
    int tid = threadIdx.x;
    int i0 = 2 * tid, i1 = 2 * tid + 1;
    int l0 = (i0 < n_res) ? c_res_len[seq[i0]] : 0;
    int l1 = (i1 < n_res) ? c_res_len[seq[i1]] : 0;
    int pair = l0 + l1;
    s[tid] = pair;
    __syncthreads();
    #pragma unroll
    for (int off = 1; off < 1024; off <<= 1) {
        int v = (tid >= off) ? s[tid - off] : 0;
        __syncthreads();
        s[tid] += v;
        __syncthreads();
    }
    int excl = s[tid] - pair;
    if (i0 < n_res) g_starts[i0] = excl;
    if (i1 < n_res) g_starts[i1] = excl + l0;
}

// scalar element from a float2 array with compile-time index
#define ELEM(arr, l) (((l) & 1) ? arr[(l) >> 1].y : arr[(l) >> 1].x)

// ---------------------------------------------------------------------------
// Templated hot path: exact trip counts for residue length L, but with the
// m-loop kept DYNAMIC (unroll 1) so the hot loop is a tiny body looping L
// times — small code footprint, good I$ locality (the R3 full-unroll version
// thrashed L0/L1.5 I$ and halved the issue rate).
// ---------------------------------------------------------------------------
template<int L>
__device__ __forceinline__ void posmix_body(
    const float2* __restrict__ sW2v,   // shared W base for this thread's v
    const float2* __restrict__ sd2d,   // shared diff base for this thread's d
    const float*  __restrict__ gWa,    // W_amn row for (t, v)
    float* __restrict__ qamn,          // out_amn + i*192 + tid   (batch 0)
    float* __restrict__ patm,          // out_atm + start*192 + tid (batch 0)
    int B, int bstride_amn, int bstride_atm)
{
    constexpr int NPL = (L + 1) / 2;   // float2 pairs covering L
    // odd L: last pair's dv.y is 0 (diff zero-padded), so garbage w.y is safe

    #pragma unroll 1
    for (int bb0 = 0; bb0 < B; bb0 += 4) {
        // pull 4 batches of this thread's diff column into registers
        float2 dv0[NPL], dv1[NPL], dv2[NPL], dv3[NPL];
        #pragma unroll
        for (int p = 0; p < NPL; p++) {
            dv0[p] = sd2d[(bb0 + 0) * 3 * NP + p];
            dv1[p] = sd2d[(bb0 + 1) * 3 * NP + p];
            dv2[p] = sd2d[(bb0 + 2) * 3 * NP + p];
            dv3[p] = sd2d[(bb0 + 3) * 3 * NP + p];
        }

        // ---- x_v_amn : exact-L scalar dot (stays in-bounds of W_amn) ----
        {
            float a0 = 0.f, a1 = 0.f, a2 = 0.f, a3 = 0.f;
            #pragma unroll
            for (int l = 0; l < L; l++) {
                float w = gWa[l];           // L1-cached, broadcast across 3 d-threads
                a0 += w * ELEM(dv0, l);
                a1 += w * ELEM(dv1, l);
                a2 += w * ELEM(dv2, l);
                a3 += w * ELEM(dv3, l);
            }
            float* q = qamn + bb0 * bstride_amn;
            q[0] = a0;
            q += bstride_amn; q[0] = a1;
            q += bstride_amn; q[0] = a2;
            q += bstride_amn; q[0] = a3;
        }

        // ---- x_v_atm : dynamic m-loop (tiny body, loops L times) ----
        float* p0 = patm + bb0 * bstride_atm;
        float* p1 = p0 + bstride_atm;
        float* p2 = p1 + bstride_atm;
        float* p3 = p2 + bstride_atm;
        const float2* wr = sW2v;
        #pragma unroll 1
        for (int m = 0; m < L; m++) {
            float a0 = 0.f, a1 = 0.f, a2 = 0.f, a3 = 0.f;
            #pragma unroll
            for (int p = 0; p < NPL; p++) {
                float2 w = wr[p];
                a0 += w.x * dv0[p].x + w.y * dv0[p].y;
                a1 += w.x * dv1[p].x + w.y * dv1[p].y;
                a2 += w.x * dv2[p].x + w.y * dv2[p].y;
                a3 += w.x * dv3[p].x + w.y * dv3[p].y;
            }
            p0[0] = a0; p1[0] = a1; p2[0] = a2; p3[0] = a3;
            p0 += DV * 3; p1 += DV * 3; p2 += DV * 3; p3 += DV * 3;
            wr += DV * NP;
        }
    }
}

// ---------------------------------------------------------------------------
// Kernel 2: fused gather + dual-einsum + scatter. One block per residue.
// ---------------------------------------------------------------------------
__global__ __launch_bounds__(TPB, 4) void posmix_kernel(
    const float* __restrict__ pos_atm,   // (B, atoms, 3)
    const float* __restrict__ pos_amn,   // (B, n_res, 3)
    const float* __restrict__ W_amn,     // (20, 64, 13)
    const float* __restrict__ W_atm,     // (20, 13, 64, 13)
    const int*   __restrict__ seq,       // (n_res,)
    float* __restrict__ out_atm,         // (B, atoms, 64, 3)
    float* __restrict__ out_amn,         // (B, n_res, 64, 3)
    int B, int n_res, int atoms)
{
    extern __shared__ float smem[];
    float* sW    = smem;                        // LMAX*DV*LPAD floats
    float* sdiff = smem + LMAX * DV * LPAD;     // B*3*LPAD floats

    const int i   = blockIdx.x;
    const int tid = threadIdx.x;
    const int t   = seq[i];
    const int L   = c_res_len[t];
    const int start = g_starts[i];

    // --- stage W_atm[t][0:L][*][*], padded rows of 14 ---
    const float* gW = W_atm + (size_t)t * (LMAX * DV * LMAX);
    const int nW = L * DV * LMAX;
    for (int idx = tid; idx < nW; idx += TPB) {
        int row = idx / LMAX;
        int l   = idx - row * LMAX;
        sW[row * LPAD + l] = gW[idx];
    }

    // --- stage diffs, layout [b][d][LPAD], zero-padded in l ---
    const int nd = B * 3 * LPAD;
    for (int idx = tid; idx < nd; idx += TPB) {
        int b = idx / (3 * LPAD);
        int r = idx - b * (3 * LPAD);
        int d = r / LPAD;
        int l = r - d * LPAD;
        float val = 0.0f;
        if (l < L) {
            val = pos_atm[((size_t)b * atoms + start + l) * 3 + d]
                - pos_amn[((size_t)b * n_res + i) * 3 + d];
        }
        sdiff[idx] = val;
    }
    __syncthreads();

    const int v = tid / 3;
    const int d = tid - v * 3;
    const float2* sW2v = (const float2*)sW + v * NP;
    const float2* sd2d = (const float2*)sdiff + d * NP;
    const float*  gWa  = W_amn + ((size_t)t * DV + v) * LMAX;

    const int bstride_atm = atoms * (DV * 3);
    const int bstride_amn = n_res * (DV * 3);

    float* qamn = out_amn + i * (DV * 3) + tid;
    float* patm = out_atm + start * (DV * 3) + tid;

    switch (L) {
        case 3:  posmix_body<3> (sW2v, sd2d, gWa, qamn, patm, B, bstride_amn, bstride_atm); break;
        case 4:  posmix_body<4> (sW2v, sd2d, gWa, qamn, patm, B, bstride_amn, bstride_atm); break;
        case 5:  posmix_body<5> (sW2v, sd2d, gWa, qamn, patm, B, bstride_amn, bstride_atm); break;
        case 6:  posmix_body<6> (sW2v, sd2d, gWa, qamn, patm, B, bstride_amn, bstride_atm); break;
        case 7:  posmix_body<7> (sW2v, sd2d, gWa, qamn, patm, B, bstride_amn, bstride_atm); break;
        case 8:  posmix_body<8> (sW2v, sd2d, gWa, qamn, patm, B, bstride_amn, bstride_atm); break;
        case 9:  posmix_body<9> (sW2v, sd2d, gWa, qamn, patm, B, bstride_amn, bstride_atm); break;
        case 10: posmix_body<10>(sW2v, sd2d, gWa, qamn, patm, B, bstride_amn, bstride_atm); break;
        case 11: posmix_body<11>(sW2v, sd2d, gWa, qamn, patm, B, bstride_amn, bstride_atm); break;
        default: posmix_body<13>(sW2v, sd2d, gWa, qamn, patm, B, bstride_amn, bstride_atm); break;
    }
}

// ---------------------------------------------------------------------------
// Launch: d_out = concat(x_v_atm.ravel(), x_v_amn.ravel())
// ---------------------------------------------------------------------------
extern "C" void kernel_launch(void* const* d_in, const int* in_sizes, int n_in,
                              void* d_out, int out_size) {
    const float* pos_atm = (const float*)d_in[0];
    const float* pos_amn = (const float*)d_in[1];
    const float* W_amn   = (const float*)d_in[2];
    const float* W_atm   = (const float*)d_in[3];
    const int*   seq     = (const int*)d_in[4];

    const int n_res = in_sizes[4];                  // 2048
    const int B     = in_sizes[1] / (n_res * 3);    // 16
    const int atoms = in_sizes[0] / (B * 3);        // 15036

    float* out_atm = (float*)d_out;
    float* out_amn = out_atm + (size_t)B * atoms * DV * 3;

    const int smem_bytes = (LMAX * DV * LPAD + 16 * 3 * LPAD) * (int)sizeof(float);
    cudaFuncSetAttribute(posmix_kernel,
                         cudaFuncAttributeMaxDynamicSharedMemorySize, smem_bytes);

    scan_starts_kernel<<<1, 1024>>>(seq, n_res);
    posmix_kernel<<<n_res, TPB, smem_bytes>>>(pos_atm, pos_amn, W_amn, W_atm, seq,
                                              out_atm, out_amn, B, n_res, atoms);
}